// round 1
// baseline (speedup 1.0000x reference)
#include <cuda_runtime.h>
#include <math.h>

// Problem constants
#define B_   2
#define LQ   1024
#define LK_  2048
#define DM   1024
#define H_   16
#define DH   64

#define OUT_ELEMS  (B_*LQ*DM)          // 2,097,152
#define ATTN_ELEMS (B_*H_*LQ*LK_)      // 67,108,864

// Scratch (allocation-free rule: __device__ globals)
__device__ float g_Q[B_*LQ*DM];        // 8 MB  projected Q, [B,Lq,D] (head-split by index)
__device__ float g_K[B_*LK_*DM];       // 16 MB projected K
__device__ float g_V[B_*LK_*DM];       // 16 MB projected V
__device__ float g_ctx[B_*LQ*DM];      // 8 MB  attention context, [B,Lq,D]

// ---------------------------------------------------------------------------
// GEMM: C[M,N] = A[M,K] @ W[N,K]^T + bias[N]   (torch Linear semantics)
// 128x128 tile, BK=16, 256 threads, 8x8 micro-tile, smem stored k-major.
// M,N,K assumed multiples of 128/128/16 (true for all calls here).
// ---------------------------------------------------------------------------
__global__ void __launch_bounds__(256) gemm_nt_bias(
    const float* __restrict__ A, const float* __restrict__ W,
    const float* __restrict__ bias, float* __restrict__ C,
    int M, int N, int K)
{
    __shared__ float As[16][132];   // [kk][m_local], pad 132 floats (528B, 16B aligned)
    __shared__ float Bs[16][132];   // [kk][n_local]

    const int t  = threadIdx.x;
    const int tx = t & 15;          // n micro index
    const int ty = t >> 4;          // m micro index
    const int m0 = blockIdx.y * 128;
    const int n0 = blockIdx.x * 128;

    const int r  = t >> 2;          // 0..63 (row within half-tile)
    const int c4 = (t & 3) << 2;    // k offset 0/4/8/12

    const float* Ap = A + (long long)(m0 + r) * K + c4;
    const float* Wp = W + (long long)(n0 + r) * K + c4;
    const long long rowOfs = (long long)64 * K;

    float acc[8][8];
#pragma unroll
    for (int i = 0; i < 8; i++)
#pragma unroll
        for (int j = 0; j < 8; j++) acc[i][j] = 0.f;

    for (int k0 = 0; k0 < K; k0 += 16) {
        float4 a0 = *(const float4*)(Ap + k0);
        float4 a1 = *(const float4*)(Ap + rowOfs + k0);
        float4 b0 = *(const float4*)(Wp + k0);
        float4 b1 = *(const float4*)(Wp + rowOfs + k0);
        __syncthreads();   // protect previous iteration's smem reads
        As[c4+0][r]    = a0.x; As[c4+1][r]    = a0.y; As[c4+2][r]    = a0.z; As[c4+3][r]    = a0.w;
        As[c4+0][r+64] = a1.x; As[c4+1][r+64] = a1.y; As[c4+2][r+64] = a1.z; As[c4+3][r+64] = a1.w;
        Bs[c4+0][r]    = b0.x; Bs[c4+1][r]    = b0.y; Bs[c4+2][r]    = b0.z; Bs[c4+3][r]    = b0.w;
        Bs[c4+0][r+64] = b1.x; Bs[c4+1][r+64] = b1.y; Bs[c4+2][r+64] = b1.z; Bs[c4+3][r+64] = b1.w;
        __syncthreads();
#pragma unroll
        for (int kk = 0; kk < 16; kk++) {
            float4 x0 = *(const float4*)&As[kk][ty*8];
            float4 x1 = *(const float4*)&As[kk][ty*8+4];
            float4 y0 = *(const float4*)&Bs[kk][tx*8];
            float4 y1 = *(const float4*)&Bs[kk][tx*8+4];
            float av[8] = {x0.x,x0.y,x0.z,x0.w,x1.x,x1.y,x1.z,x1.w};
            float bv[8] = {y0.x,y0.y,y0.z,y0.w,y1.x,y1.y,y1.z,y1.w};
#pragma unroll
            for (int i = 0; i < 8; i++)
#pragma unroll
                for (int j = 0; j < 8; j++)
                    acc[i][j] += av[i] * bv[j];
        }
    }

#pragma unroll
    for (int i = 0; i < 8; i++) {
        int m = m0 + ty*8 + i;
#pragma unroll
        for (int j = 0; j < 8; j++) {
            int n = n0 + tx*8 + j;
            C[(long long)m * N + n] = acc[i][j] + bias[n];
        }
    }
}

// ---------------------------------------------------------------------------
// Fused attention: per CTA = (q-tile of 16, head h, batch b)
//   scores = Q_h @ K_h^T / 8 + bias, mask, softmax -> attn (gmem) + sc (smem)
//   ctx    = attn @ V_h
// ---------------------------------------------------------------------------
#define TQ   16
#define KC   64
#define SPAD 65
#define ATTN_SMEM_FLOATS (TQ*LK_ + TQ*SPAD + KC*SPAD)
#define ATTN_SMEM_BYTES  (ATTN_SMEM_FLOATS * 4)

__global__ void __launch_bounds__(256) attn_kernel(
    const float* __restrict__ bias, const int* __restrict__ mask,
    float* __restrict__ attn_out)
{
    extern __shared__ float sm[];
    float* sc = sm;                       // [TQ][LK_]  scores/probs
    float* qs = sc + TQ*LK_;              // [TQ][SPAD] Q tile
    float* ks = qs + TQ*SPAD;             // [KC][SPAD] K or V chunk

    const int t  = threadIdx.x;
    const int q0 = blockIdx.x * TQ;
    const int h  = blockIdx.y;
    const int b  = blockIdx.z;

    // --- load Q tile: 16 rows x 64 floats ---
    {
        int qi = t >> 4, c = t & 15;
        float4 v = *(const float4*)&g_Q[((long long)(b*LQ + q0 + qi))*DM + h*DH + c*4];
        float* dst = &qs[qi*SPAD + c*4];
        dst[0]=v.x; dst[1]=v.y; dst[2]=v.z; dst[3]=v.w;
    }

    const int qp = t >> 5;   // 0..7  -> q pair
    const int kp = t & 31;   // 0..31 -> k pair within chunk
    const float* biasBase = bias + ((long long)((b*H_ + h)*LQ + q0)) * LK_;
    const int*   maskBase = mask + ((long long)(b*LQ + q0)) * LK_;

    // --- phase 1: scores + bias + mask ---
    for (int k0 = 0; k0 < LK_; k0 += KC) {
        __syncthreads();   // previous compute done (also covers qs store on iter 0)
        {
            int ki = t >> 2, c = t & 3;
            const float* src = &g_K[((long long)(b*LK_ + k0 + ki))*DM + h*DH];
            float* dst = &ks[ki*SPAD];
#pragma unroll
            for (int u = 0; u < 4; u++) {
                int d0 = (c + u*4) * 4;
                float4 v = *(const float4*)&src[d0];
                dst[d0]=v.x; dst[d0+1]=v.y; dst[d0+2]=v.z; dst[d0+3]=v.w;
            }
        }
        __syncthreads();

        float a00=0.f, a01=0.f, a10=0.f, a11=0.f;
        const float* q0p = &qs[(qp*2  )*SPAD];
        const float* q1p = &qs[(qp*2+1)*SPAD];
        const float* k0p = &ks[(kp*2  )*SPAD];
        const float* k1p = &ks[(kp*2+1)*SPAD];
#pragma unroll
        for (int d = 0; d < DH; d++) {
            float qa = q0p[d], qb = q1p[d];
            float ka = k0p[d], kb = k1p[d];
            a00 += qa*ka; a01 += qa*kb;
            a10 += qb*ka; a11 += qb*kb;
        }

        int qA = qp*2, qB = qA+1;
        int kA = k0 + kp*2, kB = kA+1;
        float s;
        s = a00*0.125f + biasBase[(long long)qA*LK_ + kA];
        if (maskBase[qA*LK_ + kA] == 0) s = -1e9f;
        sc[qA*LK_ + kA] = s;
        s = a01*0.125f + biasBase[(long long)qA*LK_ + kB];
        if (maskBase[qA*LK_ + kB] == 0) s = -1e9f;
        sc[qA*LK_ + kB] = s;
        s = a10*0.125f + biasBase[(long long)qB*LK_ + kA];
        if (maskBase[qB*LK_ + kA] == 0) s = -1e9f;
        sc[qB*LK_ + kA] = s;
        s = a11*0.125f + biasBase[(long long)qB*LK_ + kB];
        if (maskBase[qB*LK_ + kB] == 0) s = -1e9f;
        sc[qB*LK_ + kB] = s;
    }
    __syncthreads();

    // --- phase 2: softmax per row (16 threads per row) + write attn ---
    {
        const int row = t >> 4, g = t & 15;
        float* srow = &sc[row*LK_];

        float m = -3.4e38f;
        for (int k = g; k < LK_; k += 16) m = fmaxf(m, srow[k]);
#pragma unroll
        for (int off = 8; off; off >>= 1) m = fmaxf(m, __shfl_xor_sync(0xffffffffu, m, off, 16));

        float l = 0.f;
        for (int k = g; k < LK_; k += 16) {
            float p = __expf(fmaxf(srow[k] - m, -80.f));
            srow[k] = p;
            l += p;
        }
#pragma unroll
        for (int off = 8; off; off >>= 1) l += __shfl_xor_sync(0xffffffffu, l, off, 16);

        float inv = 1.f / l;
        float* arow = attn_out ? attn_out + ((long long)((b*H_ + h)*LQ + q0 + row)) * LK_ : (float*)0;
        for (int k = g; k < LK_; k += 16) {
            float p = srow[k] * inv;
            srow[k] = p;
            if (arow) arow[k] = p;
        }
    }

    // --- phase 3: ctx = attn @ V_h ---
    {
        const int qr = t >> 4;   // 0..15
        const int dq = t & 15;   // d = dq*4
        float c0=0.f, c1=0.f, c2=0.f, c3=0.f;
        for (int k0 = 0; k0 < LK_; k0 += KC) {
            __syncthreads();   // softmax/compute readers done before overwriting ks
            {
                int ki = t >> 2, c = t & 3;
                const float* src = &g_V[((long long)(b*LK_ + k0 + ki))*DM + h*DH];
                float* dst = &ks[ki*SPAD];
#pragma unroll
                for (int u = 0; u < 4; u++) {
                    int d0 = (c + u*4) * 4;
                    float4 v = *(const float4*)&src[d0];
                    dst[d0]=v.x; dst[d0+1]=v.y; dst[d0+2]=v.z; dst[d0+3]=v.w;
                }
            }
            __syncthreads();
            const float* srow = &sc[qr*LK_ + k0];
#pragma unroll
            for (int kk = 0; kk < KC; kk++) {
                float p = srow[kk];
                const float* v = &ks[kk*SPAD + dq*4];
                c0 += p*v[0]; c1 += p*v[1]; c2 += p*v[2]; c3 += p*v[3];
            }
        }
        float4 o; o.x=c0; o.y=c1; o.z=c2; o.w=c3;
        *(float4*)&g_ctx[((long long)(b*LQ + q0 + qr))*DM + h*DH + dq*4] = o;
    }
}

// ---------------------------------------------------------------------------
extern "C" void kernel_launch(void* const* d_in, const int* in_sizes, int n_in,
                              void* d_out, int out_size)
{
    const float* query = (const float*)d_in[0];
    const float* key   = (const float*)d_in[1];
    const float* value = (const float*)d_in[2];
    const int*   mask  = (const int*)  d_in[3];
    const float* abias = (const float*)d_in[4];
    const float* Wq = (const float*)d_in[5];
    const float* bq = (const float*)d_in[6];
    const float* Wk = (const float*)d_in[7];
    const float* bk = (const float*)d_in[8];
    const float* Wv = (const float*)d_in[9];
    const float* bv = (const float*)d_in[10];
    const float* Wo = (const float*)d_in[11];
    const float* bo = (const float*)d_in[12];
    float* out = (float*)d_out;

    float *gQ, *gK, *gV, *gC;
    cudaGetSymbolAddress((void**)&gQ, g_Q);
    cudaGetSymbolAddress((void**)&gK, g_K);
    cudaGetSymbolAddress((void**)&gV, g_V);
    cudaGetSymbolAddress((void**)&gC, g_ctx);

    // attn goes after out if the harness compares the full tuple
    float* attn_ptr = (out_size >= OUT_ELEMS + ATTN_ELEMS) ? out + OUT_ELEMS : (float*)0;

    static int attr_done = 0;
    (void)attr_done; // attribute set every call; deterministic & capture-safe
    cudaFuncSetAttribute(attn_kernel, cudaFuncAttributeMaxDynamicSharedMemorySize,
                         ATTN_SMEM_BYTES);

    // Projections
    gemm_nt_bias<<<dim3(DM/128, (B_*LQ)/128), 256>>>(query, Wq, bq, gQ, B_*LQ,  DM, DM);
    gemm_nt_bias<<<dim3(DM/128, (B_*LK_)/128), 256>>>(key,   Wk, bk, gK, B_*LK_, DM, DM);
    gemm_nt_bias<<<dim3(DM/128, (B_*LK_)/128), 256>>>(value, Wv, bv, gV, B_*LK_, DM, DM);

    // Attention (scores + softmax + attn output + context)
    attn_kernel<<<dim3(LQ/TQ, H_, B_), 256, ATTN_SMEM_BYTES>>>(abias, mask, attn_ptr);

    // Output projection
    gemm_nt_bias<<<dim3(DM/128, (B_*LQ)/128), 256>>>(gC, Wo, bo, out, B_*LQ, DM, DM);
}